// round 14
// baseline (speedup 1.0000x reference)
#include <cuda_runtime.h>
#include <cuda_fp16.h>
#include <math.h>
#include <stdint.h>

// Problem constants
#define BATCH 2
#define SEQ   2048
#define DMODEL 2048
#define NHEADS 32
#define NKVH   4
#define HDIM   64
#define GQA_REP (NHEADS / NKVH)   // 8
#define MROWS (BATCH * SEQ)       // 4096
#define QKVN  (DMODEL + 2 * NKVH * HDIM)   // 2560 merged [Q|K|V] N

// Scratch (device globals; no runtime allocation allowed)
__device__ __half g_xh[MROWS * DMODEL];
__device__ __half g_qh[MROWS * NHEADS * HDIM];   // rope'd, scaled, half
__device__ __half g_kh[MROWS * NKVH * HDIM];     // rope'd K half [4096,256]
__device__ __half g_vt[NKVH * HDIM * MROWS];     // V^T half [256,4096] (GEMM writes direct)
__device__ __half g_aoh[MROWS * NHEADS * HDIM];  // attention out, half
__device__ __half g_wqkvTh[QKVN * DMODEL];       // merged (N,K) k-major half
__device__ __half g_woTh[DMODEL * DMODEL];

// ---------------------------------------------------------------------------
// helpers
// ---------------------------------------------------------------------------
__device__ __forceinline__ uint32_t smem_u32(const void* p) {
    uint32_t a;
    asm("{ .reg .u64 t; cvta.to.shared.u64 t, %1; cvt.u32.u64 %0, t; }"
        : "=r"(a) : "l"(p));
    return a;
}
__device__ __forceinline__ float fexp2(float x) {
    float y;
    asm("ex2.approx.ftz.f32 %0, %1;" : "=f"(y) : "f"(x));
    return y;
}
__device__ __forceinline__ uint32_t packh2(float lo, float hi) {
    __half2 h = __floats2half2_rn(lo, hi);
    return *reinterpret_cast<uint32_t*>(&h);
}
__device__ __forceinline__ void mma_f16(float* d, const uint32_t* a, const uint32_t* b) {
    asm volatile(
        "mma.sync.aligned.m16n8k16.row.col.f32.f16.f16.f32 "
        "{%0,%1,%2,%3}, {%4,%5,%6,%7}, {%8,%9}, {%0,%1,%2,%3};"
        : "+f"(d[0]), "+f"(d[1]), "+f"(d[2]), "+f"(d[3])
        : "r"(a[0]), "r"(a[1]), "r"(a[2]), "r"(a[3]), "r"(b[0]), "r"(b[1]));
}
__device__ __forceinline__ void ldsm4(uint32_t* r, uint32_t addr) {
    asm volatile("ldmatrix.sync.aligned.m8n8.x4.shared.b16 {%0,%1,%2,%3}, [%4];"
                 : "=r"(r[0]), "=r"(r[1]), "=r"(r[2]), "=r"(r[3]) : "r"(addr));
}
__device__ __forceinline__ void cp16(uint32_t saddr, const void* g) {
    asm volatile("cp.async.cg.shared.global [%0], [%1], 16;" :: "r"(saddr), "l"(g));
}
#define CP_COMMIT() asm volatile("cp.async.commit_group;" ::: "memory")
#define CP_WAIT1()  asm volatile("cp.async.wait_group 1;" ::: "memory")

// ---------------------------------------------------------------------------
// Merged prep kernel (one launch, z selects work):
//   z=0..3: weight transposes to k-major half; z=4,5: x fp32->half copy.
// ---------------------------------------------------------------------------
__global__ void prep_kernel(const float* __restrict__ x,
                            const float* __restrict__ wq,
                            const float* __restrict__ wk,
                            const float* __restrict__ wv,
                            const float* __restrict__ wo,
                            __half* __restrict__ xh,
                            __half* __restrict__ wqkvT,
                            __half* __restrict__ woT)
{
    const int z = blockIdx.z;
    const int x_ = threadIdx.x, y_ = threadIdx.y;  // 32 x 8

    if (z >= 4) {
        const int r0 = (z - 4) * 2048 + blockIdx.y * 32;
        const int c0 = blockIdx.x * 32;
        #pragma unroll
        for (int j = 0; j < 4; j++) {
            int r = r0 + y_ + 8 * j;
            xh[(size_t)r * DMODEL + c0 + x_] =
                __float2half_rn(x[(size_t)r * DMODEL + c0 + x_]);
        }
        return;
    }

    const float* in;
    __half* out;
    int C;
    if (z == 0)      { in = wq; out = wqkvT;                                   C = DMODEL; }
    else if (z == 1) { in = wk; out = wqkvT + (size_t)DMODEL * DMODEL;         C = NKVH * HDIM; }
    else if (z == 2) { in = wv; out = wqkvT + (size_t)(DMODEL + NKVH * HDIM) * DMODEL; C = NKVH * HDIM; }
    else             { in = wo; out = woT;                                     C = DMODEL; }

    int c0 = blockIdx.x * 32, r0 = blockIdx.y * 32;
    if (c0 >= C) return;

    __shared__ float t[32][33];
    #pragma unroll
    for (int j = 0; j < 4; j++)
        t[y_ + 8 * j][x_] = in[(size_t)(r0 + y_ + 8 * j) * C + c0 + x_];
    __syncthreads();
    #pragma unroll
    for (int j = 0; j < 4; j++)
        out[(size_t)(c0 + y_ + 8 * j) * DMODEL + r0 + x_] = __float2half_rn(t[x_][y_ + 8 * j]);
}

// ---------------------------------------------------------------------------
// fp16 mma.sync GEMM: CTA 128x128, 4 warps (2x2), warp tile 64x64, BK=64.
// 3-stage cp.async; fragments via ldmatrix.x4 (8 LDSM per kstep vs 32 LDS).
// Epilogue modes: 0 = fp32 C;
//   3 = merged QKV dispatch by n0: [0,2048) rope+scale Q (ld 2048);
//       [2048,2304) rope K (ld 256); [2304,2560) V written TRANSPOSED to vt.
// ---------------------------------------------------------------------------
#define MM_BM 128
#define MM_BN 128
#define MM_BKH 64
#define MM_STRW 36
#define MM_THREADS 128
#define MM_TILE_W (MM_BM * MM_STRW)            // 4608 words
#define MM_STAGE_W (2 * MM_TILE_W)             // 9216
#define MM_STAGES 3
#define MM_SMEM_BYTES (MM_STAGES * MM_STAGE_W * 4)   // 110592

__global__ __launch_bounds__(MM_THREADS)
void mma_gemm_f16_kernel(int M, int N, int K,
                         const __half* __restrict__ A,
                         const __half* __restrict__ BT,
                         float* __restrict__ C,
                         __half* __restrict__ Qout,
                         __half* __restrict__ Kout,
                         __half* __restrict__ VTout,
                         const float* __restrict__ freqs,
                         int mode, float qscale)
{
    extern __shared__ uint32_t sm_u[];
    const uint32_t sbase = smem_u32(sm_u);

    const int tid  = threadIdx.x;
    const int warp = tid >> 5;
    const int lane = tid & 31;
    const int g    = lane >> 2;
    const int tig  = lane & 3;

    const int wm = (warp >> 1) * 64;   // 0 or 64
    const int wn = (warp & 1) * 64;    // 0 or 64

    const int m0 = blockIdx.y * MM_BM;
    const int n0 = blockIdx.x * MM_BN;

    const int lr = tid >> 3;        // 0..15
    const int lc = tid & 7;         // 0..7

    // ldmatrix lane-invariant offsets (words)
    const int a_row = wm + (lane & 15);           // + mt*16
    const int a_wof = (lane >> 4) * 4;            // + k0
    const int b_row = wn + (lane & 7) + ((lane >> 4) * 8);  // + ntp*16
    const int b_wof = ((lane >> 3) & 1) * 4;      // + k0

    auto issue = [&](int c, int slot) {
        const uint32_t sa = sbase + 4u * (slot * MM_STAGE_W);
        #pragma unroll
        for (int j = 0; j < 8; j++) {
            int r = lr + j * 16;
            cp16(sa + 4u * (r * MM_STRW + lc * 4),
                 A + (size_t)(m0 + r) * K + c * MM_BKH + lc * 8);
            cp16(sa + 4u * (MM_TILE_W + r * MM_STRW + lc * 4),
                 BT + (size_t)(n0 + r) * K + c * MM_BKH + lc * 8);
        }
    };

    const int NC = K / MM_BKH;   // 32
    issue(0, 0); CP_COMMIT();
    issue(1, 1); CP_COMMIT();

    float acc[4][8][4] = {};

    for (int c = 0; c < NC; c++) {
        CP_WAIT1();
        __syncthreads();
        if (c + 2 < NC) issue(c + 2, (c + 2) % MM_STAGES);
        CP_COMMIT();

        const uint32_t aS = sbase + 4u * ((c % MM_STAGES) * MM_STAGE_W);
        const uint32_t bS = aS + 4u * MM_TILE_W;
        #pragma unroll
        for (int ks = 0; ks < 4; ks++) {           // 4 ksteps of k16
            const int k0 = ks * 8;
            uint32_t af[4][4], bf[8][2];
            #pragma unroll
            for (int mt = 0; mt < 4; mt++)
                ldsm4(af[mt], aS + 4u * ((a_row + mt * 16) * MM_STRW + k0 + a_wof));
            #pragma unroll
            for (int ntp = 0; ntp < 4; ntp++) {
                uint32_t t4[4];
                ldsm4(t4, bS + 4u * ((b_row + ntp * 16) * MM_STRW + k0 + b_wof));
                bf[2 * ntp][0] = t4[0];
                bf[2 * ntp][1] = t4[1];
                bf[2 * ntp + 1][0] = t4[2];
                bf[2 * ntp + 1][1] = t4[3];
            }
            #pragma unroll
            for (int mt = 0; mt < 4; mt++)
                #pragma unroll
                for (int nt = 0; nt < 8; nt++)
                    mma_f16(acc[mt][nt], af[mt], bf[nt]);
        }
    }

    // ---- epilogue
    if (mode == 0) {
        #pragma unroll
        for (int mt = 0; mt < 4; mt++) {
            const int row = m0 + wm + mt * 16 + g;
            #pragma unroll
            for (int nt = 0; nt < 8; nt++) {
                const int col = n0 + wn + nt * 8 + tig * 2;
                *(float2*)(C + (size_t)row * N + col) =
                    make_float2(acc[mt][nt][0], acc[mt][nt][1]);
                *(float2*)(C + (size_t)(row + 8) * N + col) =
                    make_float2(acc[mt][nt][2], acc[mt][nt][3]);
            }
        }
    } else if (n0 < DMODEL + NKVH * HDIM) {
        // rope branch: Q (n0 < 2048) or K (2048 <= n0 < 2304)
        const bool isQ = (n0 < DMODEL);
        __half* Out = isQ ? Qout : Kout;
        const int ldo = isQ ? DMODEL : (NKVH * HDIM);
        const int cb  = isQ ? 0 : DMODEL;
        const float scale = isQ ? qscale : 1.0f;
        #pragma unroll
        for (int mt = 0; mt < 4; mt++) {
            const int row = m0 + wm + mt * 16 + g;
            const int s0 = row & (SEQ - 1);
            const int s1 = (row + 8) & (SEQ - 1);
            #pragma unroll
            for (int nt = 0; nt < 8; nt++) {
                const int ccol = n0 + wn + nt * 8 + tig * 2 - cb;
                const int i = (ccol & 63) >> 1;
                float2 cs0 = *(const float2*)(freqs + s0 * HDIM + i * 2);
                float2 cs1 = *(const float2*)(freqs + s1 * HDIM + i * 2);
                float xr = acc[mt][nt][0], xi = acc[mt][nt][1];
                *(uint32_t*)(Out + (size_t)row * ldo + ccol) =
                    packh2((xr * cs0.x - xi * cs0.y) * scale,
                           (xr * cs0.y + xi * cs0.x) * scale);
                xr = acc[mt][nt][2]; xi = acc[mt][nt][3];
                *(uint32_t*)(Out + (size_t)(row + 8) * ldo + ccol) =
                    packh2((xr * cs1.x - xi * cs1.y) * scale,
                           (xr * cs1.y + xi * cs1.x) * scale);
            }
        }
    } else {
        // V columns: write TRANSPOSED directly into vt [256, 4096]
        #pragma unroll
        for (int mt = 0; mt < 4; mt++) {
            const int row = m0 + wm + mt * 16 + g;
            #pragma unroll
            for (int nt = 0; nt < 8; nt++) {
                const int ccol = n0 + wn + nt * 8 + tig * 2 - (DMODEL + NKVH * HDIM);
                VTout[(size_t)ccol * MROWS + row] =
                    __float2half_rn(acc[mt][nt][0]);
                VTout[(size_t)(ccol + 1) * MROWS + row] =
                    __float2half_rn(acc[mt][nt][1]);
                VTout[(size_t)ccol * MROWS + row + 8] =
                    __float2half_rn(acc[mt][nt][2]);
                VTout[(size_t)(ccol + 1) * MROWS + row + 8] =
                    __float2half_rn(acc[mt][nt][3]);
            }
        }
    }
}

// ---------------------------------------------------------------------------
// FlashAttention-2 on fp16 mma.sync. P in registers (C-frag == A-frag layout).
// 3-stage K/V cp.async pipeline, ONE barrier per kt; K/V fragments via LDSM.
// Smem (words): K 3x2304, V 3x2304 = 13824 (55296 B); Q staged in K slots 0-1.
// ---------------------------------------------------------------------------
#define FA_QT 128
#define FA_KT 64
#define FA_THREADS 256
#define FA_STRW 36
#define FA_KSLOT_W (FA_KT * FA_STRW)        // 2304
#define FA_VBASE (3 * FA_KSLOT_W)           // 6912
#define FA_SMEM_W (6 * FA_KSLOT_W)          // 13824
#define FA_SMEM_BYTES (FA_SMEM_W * 4)       // 55296

__global__ __launch_bounds__(FA_THREADS, 2)
void fa_kernel(const __half* __restrict__ Q,
               const __half* __restrict__ K,
               const __half* __restrict__ Vt,
               __half* __restrict__ O)
{
    extern __shared__ uint32_t smf[];
    const uint32_t sbase = smem_u32(smf);

    const int tid  = threadIdx.x;
    const int warp = tid >> 5;
    const int lane = tid & 31;
    const int g    = lane >> 2;
    const int tig  = lane & 3;

    const int qt = (gridDim.x - 1) - blockIdx.x;   // heavy tiles first
    const int h  = blockIdx.y;
    const int b  = blockIdx.z;
    const int kvh = h / GQA_REP;

    const int qrow0 = qt * FA_QT;
    const int wrow  = warp * 16;

    // ldmatrix lane-invariant offsets (B-fragment pattern)
    const int b_row = (lane & 7) + ((lane >> 4) * 8);       // + ntp*16
    const int b_wof = ((lane >> 3) & 1) * 4;                // + k0

    // --- stage Q tile in K-slot-0/1 region (128 rows x 32 words)
    {
        const __half* Qg = Q + (size_t)(b * SEQ + qrow0) * (NHEADS * HDIM) + h * HDIM;
        #pragma unroll
        for (int it = 0; it < 4; it++) {
            int idx = tid + it * FA_THREADS;
            int r = idx >> 3, c = idx & 7;
            *(uint4*)(smf + r * FA_STRW + c * 4) =
                *(const uint4*)(Qg + (size_t)r * (NHEADS * HDIM) + c * 8);
        }
    }
    __syncthreads();

    // --- hoist Q fragments (4 ksteps of k16) via LDSM (A-fragment pattern)
    uint32_t qf[4][4];
    {
        const int a_row = wrow + (lane & 15);
        const int a_wof = (lane >> 4) * 4;
        #pragma unroll
        for (int ks = 0; ks < 4; ks++)
            ldsm4(qf[ks], sbase + 4u * (a_row * FA_STRW + ks * 8 + a_wof));
    }
    __syncthreads();   // Q region freed -> K slots

    const __half* Kb0 = K + (size_t)(b * SEQ) * (NKVH * HDIM) + kvh * HDIM;
    const __half* Vb0 = Vt + (size_t)(kvh * HDIM) * MROWS + b * SEQ;

    auto issue = [&](int kt_, int slot) {
        #pragma unroll
        for (int it = 0; it < 2; it++) {
            int idx = tid + it * FA_THREADS;
            int r = idx >> 3, c = idx & 7;
            cp16(sbase + 4u * (slot * FA_KSLOT_W + r * FA_STRW + c * 4),
                 Kb0 + (size_t)(kt_ * FA_KT + r) * (NKVH * HDIM) + c * 8);
            cp16(sbase + 4u * (FA_VBASE + slot * FA_KSLOT_W + r * FA_STRW + c * 4),
                 Vb0 + (size_t)r * MROWS + kt_ * FA_KT + c * 8);
        }
    };

    const int nkt = 2 * qt + 2;
    issue(0, 0); CP_COMMIT();
    issue(1, 1); CP_COMMIT();

    float m0r = -1e30f, m1r = -1e30f;
    float l0r = 0.0f,  l1r = 0.0f;
    float o[8][4] = {};

    for (int kt = 0; kt < nkt; kt++) {
        CP_WAIT1();
        __syncthreads();   // slot (kt+2)%3 drained; data for kt visible
        if (kt + 2 < nkt) issue(kt + 2, (kt + 2) % 3);
        CP_COMMIT();

        const int slot = kt % 3;
        const uint32_t kS = sbase + 4u * (slot * FA_KSLOT_W);
        const uint32_t vS = sbase + 4u * (FA_VBASE + slot * FA_KSLOT_W);

        const bool active = (kt * FA_KT <= qrow0 + wrow + 15);
        if (active) {
            // S = Q K^T  (K fragments via LDSM)
            float s[8][4] = {};
            #pragma unroll
            for (int ks = 0; ks < 4; ks++) {
                const int k0 = ks * 8;
                uint32_t bf[8][2];
                #pragma unroll
                for (int ntp = 0; ntp < 4; ntp++) {
                    uint32_t t4[4];
                    ldsm4(t4, kS + 4u * ((b_row + ntp * 16) * FA_STRW + k0 + b_wof));
                    bf[2 * ntp][0] = t4[0];
                    bf[2 * ntp][1] = t4[1];
                    bf[2 * ntp + 1][0] = t4[2];
                    bf[2 * ntp + 1][1] = t4[3];
                }
                #pragma unroll
                for (int nt = 0; nt < 8; nt++)
                    mma_f16(s[nt], qf[ks], bf[nt]);
            }

            // causal mask on diagonal-straddling tiles
            if (kt * FA_KT + (FA_KT - 1) > qrow0 + wrow) {
                const int rg  = qrow0 + wrow + g;
                const int rg8 = rg + 8;
                #pragma unroll
                for (int nt = 0; nt < 8; nt++) {
                    const int c0 = kt * FA_KT + nt * 8 + 2 * tig;
                    const int c1 = c0 + 1;
                    if (c0 > rg)  s[nt][0] = -1e30f;
                    if (c1 > rg)  s[nt][1] = -1e30f;
                    if (c0 > rg8) s[nt][2] = -1e30f;
                    if (c1 > rg8) s[nt][3] = -1e30f;
                }
            }

            // online softmax (log2 domain); p overwrites s in registers
            float mx0 = -1e30f, mx1 = -1e30f;
            #pragma unroll
            for (int nt = 0; nt < 8; nt++) {
                mx0 = fmaxf(mx0, fmaxf(s[nt][0], s[nt][1]));
                mx1 = fmaxf(mx1, fmaxf(s[nt][2], s[nt][3]));
            }
            mx0 = fmaxf(mx0, __shfl_xor_sync(0xffffffffu, mx0, 1));
            mx0 = fmaxf(mx0, __shfl_xor_sync(0xffffffffu, mx0, 2));
            mx1 = fmaxf(mx1, __shfl_xor_sync(0xffffffffu, mx1, 1));
            mx1 = fmaxf(mx1, __shfl_xor_sync(0xffffffffu, mx1, 2));

            const float mn0 = fmaxf(m0r, mx0);
            const float mn1 = fmaxf(m1r, mx1);
            const float al0 = fexp2(m0r - mn0);
            const float al1 = fexp2(m1r - mn1);
            m0r = mn0; m1r = mn1;

            float sum0 = 0.0f, sum1 = 0.0f;
            #pragma unroll
            for (int nt = 0; nt < 8; nt++) {
                s[nt][0] = fexp2(s[nt][0] - mn0);
                s[nt][1] = fexp2(s[nt][1] - mn0);
                s[nt][2] = fexp2(s[nt][2] - mn1);
                s[nt][3] = fexp2(s[nt][3] - mn1);
                sum0 += s[nt][0] + s[nt][1];
                sum1 += s[nt][2] + s[nt][3];
            }
            sum0 += __shfl_xor_sync(0xffffffffu, sum0, 1);
            sum0 += __shfl_xor_sync(0xffffffffu, sum0, 2);
            sum1 += __shfl_xor_sync(0xffffffffu, sum1, 1);
            sum1 += __shfl_xor_sync(0xffffffffu, sum1, 2);
            l0r = l0r * al0 + sum0;
            l1r = l1r * al1 + sum1;

            #pragma unroll
            for (int nt = 0; nt < 8; nt++) {
                o[nt][0] *= al0; o[nt][1] *= al0;
                o[nt][2] *= al1; o[nt][3] *= al1;
            }

            // O += P V : P packed straight from registers; V fragments via LDSM
            #pragma unroll
            for (int ks = 0; ks < 4; ks++) {
                const int k0 = ks * 8;
                uint32_t a[4];
                a[0] = packh2(s[2 * ks][0],     s[2 * ks][1]);
                a[1] = packh2(s[2 * ks][2],     s[2 * ks][3]);
                a[2] = packh2(s[2 * ks + 1][0], s[2 * ks + 1][1]);
                a[3] = packh2(s[2 * ks + 1][2], s[2 * ks + 1][3]);
                uint32_t bf[8][2];
                #pragma unroll
                for (int ntp = 0; ntp < 4; ntp++) {
                    uint32_t t4[4];
                    ldsm4(t4, vS + 4u * ((b_row + ntp * 16) * FA_STRW + k0 + b_wof));
                    bf[2 * ntp][0] = t4[0];
                    bf[2 * ntp][1] = t4[1];
                    bf[2 * ntp + 1][0] = t4[2];
                    bf[2 * ntp + 1][1] = t4[3];
                }
                #pragma unroll
                for (int nt = 0; nt < 8; nt++)
                    mma_f16(o[nt], a, bf[nt]);
            }
        }
    }

    // epilogue: normalize, write half (feeds wo GEMM)
    const float il0 = 1.0f / l0r;
    const float il1 = 1.0f / l1r;
    __half* Ob = O + (size_t)(b * SEQ + qrow0 + wrow) * (NHEADS * HDIM) + h * HDIM;
    #pragma unroll
    for (int nt = 0; nt < 8; nt++) {
        *(__half2*)(Ob + (size_t)g * (NHEADS * HDIM) + nt * 8 + 2 * tig) =
            __floats2half2_rn(o[nt][0] * il0, o[nt][1] * il0);
        *(__half2*)(Ob + (size_t)(g + 8) * (NHEADS * HDIM) + nt * 8 + 2 * tig) =
            __floats2half2_rn(o[nt][2] * il1, o[nt][3] * il1);
    }
}

// ---------------------------------------------------------------------------
// launch
// ---------------------------------------------------------------------------
extern "C" void kernel_launch(void* const* d_in, const int* in_sizes, int n_in,
                              void* d_out, int out_size)
{
    const float* x     = (const float*)d_in[0];
    const float* freqs = (const float*)d_in[1];
    // d_in[2] is the additive mask — exactly causal; handled in-kernel.
    const float* wq    = (const float*)d_in[3];
    const float* wk    = (const float*)d_in[4];
    const float* wv    = (const float*)d_in[5];
    const float* wo    = (const float*)d_in[6];
    float* out = (float*)d_out;

    static __half *xh = nullptr, *qh = nullptr, *kh = nullptr,
                  *vt = nullptr, *aoh = nullptr;
    static __half *wqkvTh = nullptr, *woTh = nullptr;
    if (!xh) {
        cudaGetSymbolAddress((void**)&xh,     g_xh);
        cudaGetSymbolAddress((void**)&qh,     g_qh);
        cudaGetSymbolAddress((void**)&kh,     g_kh);
        cudaGetSymbolAddress((void**)&vt,     g_vt);
        cudaGetSymbolAddress((void**)&aoh,    g_aoh);
        cudaGetSymbolAddress((void**)&wqkvTh, g_wqkvTh);
        cudaGetSymbolAddress((void**)&woTh,   g_woTh);
        cudaFuncSetAttribute(mma_gemm_f16_kernel, cudaFuncAttributeMaxDynamicSharedMemorySize,
                             MM_SMEM_BYTES);
        cudaFuncSetAttribute(fa_kernel, cudaFuncAttributeMaxDynamicSharedMemorySize,
                             FA_SMEM_BYTES);
    }

    const float qscale = 0.18033688011112042f;  // 0.125 * log2(e)

    // single prep launch: x conversion + all 4 weight transposes
    prep_kernel<<<dim3(64, 64, 6), dim3(32, 8)>>>(x, wq, wk, wv, wo, xh, wqkvTh, woTh);

    // merged QKV projection (fused rope/scale/half epilogues; V written transposed)
    mma_gemm_f16_kernel<<<dim3(QKVN / MM_BN, MROWS / MM_BM), MM_THREADS, MM_SMEM_BYTES>>>(
        MROWS, QKVN, DMODEL, xh, wqkvTh, nullptr, qh, kh, vt, freqs, 3, qscale);

    // attention
    fa_kernel<<<dim3(SEQ / FA_QT, NHEADS, BATCH), FA_THREADS, FA_SMEM_BYTES>>>(qh, kh, vt, aoh);

    // output projection (fp32 epilogue straight to d_out)
    mma_gemm_f16_kernel<<<dim3(DMODEL / MM_BN, MROWS / MM_BM), MM_THREADS, MM_SMEM_BYTES>>>(
        MROWS, DMODEL, DMODEL, aoh, woTh, out, nullptr, nullptr, nullptr, nullptr, 0, 1.0f);
}

// round 15
// speedup vs baseline: 1.0962x; 1.0962x over previous
#include <cuda_runtime.h>
#include <cuda_fp16.h>
#include <math.h>
#include <stdint.h>

// Problem constants
#define BATCH 2
#define SEQ   2048
#define DMODEL 2048
#define NHEADS 32
#define NKVH   4
#define HDIM   64
#define GQA_REP (NHEADS / NKVH)   // 8
#define MROWS (BATCH * SEQ)       // 4096
#define QKVN  (DMODEL + 2 * NKVH * HDIM)   // 2560 merged [Q|K|V] N

// Scratch (device globals; no runtime allocation allowed)
__device__ __half g_xh[MROWS * DMODEL];
__device__ __half g_qh[MROWS * NHEADS * HDIM];   // rope'd, scaled, half
__device__ __half g_kh[MROWS * NKVH * HDIM];     // rope'd K half [4096,256]
__device__ __half g_vt[NKVH * HDIM * MROWS];     // V^T half [256,4096] (GEMM writes direct)
__device__ __half g_aoh[MROWS * NHEADS * HDIM];  // attention out, half
__device__ __half g_wqkvTh[QKVN * DMODEL];       // merged (N,K) k-major half
__device__ __half g_woTh[DMODEL * DMODEL];

// ---------------------------------------------------------------------------
// helpers
// ---------------------------------------------------------------------------
__device__ __forceinline__ uint32_t smem_u32(const void* p) {
    uint32_t a;
    asm("{ .reg .u64 t; cvta.to.shared.u64 t, %1; cvt.u32.u64 %0, t; }"
        : "=r"(a) : "l"(p));
    return a;
}
__device__ __forceinline__ float fexp2(float x) {
    float y;
    asm("ex2.approx.ftz.f32 %0, %1;" : "=f"(y) : "f"(x));
    return y;
}
__device__ __forceinline__ uint32_t packh2(float lo, float hi) {
    __half2 h = __floats2half2_rn(lo, hi);
    return *reinterpret_cast<uint32_t*>(&h);
}
__device__ __forceinline__ void mma_f16(float* d, const uint32_t* a, const uint32_t* b) {
    asm volatile(
        "mma.sync.aligned.m16n8k16.row.col.f32.f16.f16.f32 "
        "{%0,%1,%2,%3}, {%4,%5,%6,%7}, {%8,%9}, {%0,%1,%2,%3};"
        : "+f"(d[0]), "+f"(d[1]), "+f"(d[2]), "+f"(d[3])
        : "r"(a[0]), "r"(a[1]), "r"(a[2]), "r"(a[3]), "r"(b[0]), "r"(b[1]));
}
__device__ __forceinline__ void ldsm4(uint32_t* r, uint32_t addr) {
    asm volatile("ldmatrix.sync.aligned.m8n8.x4.shared.b16 {%0,%1,%2,%3}, [%4];"
                 : "=r"(r[0]), "=r"(r[1]), "=r"(r[2]), "=r"(r[3]) : "r"(addr));
}
__device__ __forceinline__ void cp16(uint32_t saddr, const void* g) {
    asm volatile("cp.async.cg.shared.global [%0], [%1], 16;" :: "r"(saddr), "l"(g));
}
#define CP_COMMIT() asm volatile("cp.async.commit_group;" ::: "memory")
#define CP_WAIT1()  asm volatile("cp.async.wait_group 1;" ::: "memory")

// ---------------------------------------------------------------------------
// Merged prep kernel (one launch, z selects work):
//   z=0..3: weight transposes to k-major half; z=4,5: x fp32->half copy.
// ---------------------------------------------------------------------------
__global__ void prep_kernel(const float* __restrict__ x,
                            const float* __restrict__ wq,
                            const float* __restrict__ wk,
                            const float* __restrict__ wv,
                            const float* __restrict__ wo,
                            __half* __restrict__ xh,
                            __half* __restrict__ wqkvT,
                            __half* __restrict__ woT)
{
    const int z = blockIdx.z;
    const int x_ = threadIdx.x, y_ = threadIdx.y;  // 32 x 8

    if (z >= 4) {
        const int r0 = (z - 4) * 2048 + blockIdx.y * 32;
        const int c0 = blockIdx.x * 32;
        #pragma unroll
        for (int j = 0; j < 4; j++) {
            int r = r0 + y_ + 8 * j;
            xh[(size_t)r * DMODEL + c0 + x_] =
                __float2half_rn(x[(size_t)r * DMODEL + c0 + x_]);
        }
        return;
    }

    const float* in;
    __half* out;
    int C;
    if (z == 0)      { in = wq; out = wqkvT;                                   C = DMODEL; }
    else if (z == 1) { in = wk; out = wqkvT + (size_t)DMODEL * DMODEL;         C = NKVH * HDIM; }
    else if (z == 2) { in = wv; out = wqkvT + (size_t)(DMODEL + NKVH * HDIM) * DMODEL; C = NKVH * HDIM; }
    else             { in = wo; out = woT;                                     C = DMODEL; }

    int c0 = blockIdx.x * 32, r0 = blockIdx.y * 32;
    if (c0 >= C) return;

    __shared__ float t[32][33];
    #pragma unroll
    for (int j = 0; j < 4; j++)
        t[y_ + 8 * j][x_] = in[(size_t)(r0 + y_ + 8 * j) * C + c0 + x_];
    __syncthreads();
    #pragma unroll
    for (int j = 0; j < 4; j++)
        out[(size_t)(c0 + y_ + 8 * j) * DMODEL + r0 + x_] = __float2half_rn(t[x_][y_ + 8 * j]);
}

// ---------------------------------------------------------------------------
// fp16 mma.sync GEMM: CTA 128x128, 4 warps (2x2), warp tile 64x64, BK=64.
// 2-stage cp.async (73.7KB smem -> 2 CTAs/SM, 2 warps/SMSP for latency cover);
// fragments via ldmatrix.x4.
// Epilogue modes: 0 = fp32 C;
//   3 = merged QKV dispatch by n0: [0,2048) rope+scale Q (ld 2048);
//       [2048,2304) rope K (ld 256); [2304,2560) V written TRANSPOSED to vt.
// ---------------------------------------------------------------------------
#define MM_BM 128
#define MM_BN 128
#define MM_BKH 64
#define MM_STRW 36
#define MM_THREADS 128
#define MM_TILE_W (MM_BM * MM_STRW)            // 4608 words
#define MM_STAGE_W (2 * MM_TILE_W)             // 9216
#define MM_STAGES 2
#define MM_SMEM_BYTES (MM_STAGES * MM_STAGE_W * 4)   // 73728

__global__ __launch_bounds__(MM_THREADS, 2)
void mma_gemm_f16_kernel(int M, int N, int K,
                         const __half* __restrict__ A,
                         const __half* __restrict__ BT,
                         float* __restrict__ C,
                         __half* __restrict__ Qout,
                         __half* __restrict__ Kout,
                         __half* __restrict__ VTout,
                         const float* __restrict__ freqs,
                         int mode, float qscale)
{
    extern __shared__ uint32_t sm_u[];
    const uint32_t sbase = smem_u32(sm_u);

    const int tid  = threadIdx.x;
    const int warp = tid >> 5;
    const int lane = tid & 31;
    const int g    = lane >> 2;
    const int tig  = lane & 3;

    const int wm = (warp >> 1) * 64;   // 0 or 64
    const int wn = (warp & 1) * 64;    // 0 or 64

    const int m0 = blockIdx.y * MM_BM;
    const int n0 = blockIdx.x * MM_BN;

    const int lr = tid >> 3;        // 0..15
    const int lc = tid & 7;         // 0..7

    // ldmatrix lane-invariant offsets (words)
    const int a_row = wm + (lane & 15);           // + mt*16
    const int a_wof = (lane >> 4) * 4;            // + k0
    const int b_row = wn + (lane & 7) + ((lane >> 4) * 8);  // + ntp*16
    const int b_wof = ((lane >> 3) & 1) * 4;      // + k0

    auto issue = [&](int c, int slot) {
        const uint32_t sa = sbase + 4u * (slot * MM_STAGE_W);
        #pragma unroll
        for (int j = 0; j < 8; j++) {
            int r = lr + j * 16;
            cp16(sa + 4u * (r * MM_STRW + lc * 4),
                 A + (size_t)(m0 + r) * K + c * MM_BKH + lc * 8);
            cp16(sa + 4u * (MM_TILE_W + r * MM_STRW + lc * 4),
                 BT + (size_t)(n0 + r) * K + c * MM_BKH + lc * 8);
        }
    };

    const int NC = K / MM_BKH;   // 32
    issue(0, 0); CP_COMMIT();
    issue(1, 1); CP_COMMIT();

    float acc[4][8][4] = {};

    for (int c = 0; c < NC; c++) {
        CP_WAIT1();          // group c complete (c+1 may still be in flight)
        __syncthreads();

        const int slot = c & 1;
        const uint32_t aS = sbase + 4u * (slot * MM_STAGE_W);
        const uint32_t bS = aS + 4u * MM_TILE_W;
        #pragma unroll
        for (int ks = 0; ks < 4; ks++) {           // 4 ksteps of k16
            const int k0 = ks * 8;
            uint32_t af[4][4], bf[8][2];
            #pragma unroll
            for (int mt = 0; mt < 4; mt++)
                ldsm4(af[mt], aS + 4u * ((a_row + mt * 16) * MM_STRW + k0 + a_wof));
            #pragma unroll
            for (int ntp = 0; ntp < 4; ntp++) {
                uint32_t t4[4];
                ldsm4(t4, bS + 4u * ((b_row + ntp * 16) * MM_STRW + k0 + b_wof));
                bf[2 * ntp][0] = t4[0];
                bf[2 * ntp][1] = t4[1];
                bf[2 * ntp + 1][0] = t4[2];
                bf[2 * ntp + 1][1] = t4[3];
            }
            #pragma unroll
            for (int mt = 0; mt < 4; mt++)
                #pragma unroll
                for (int nt = 0; nt < 8; nt++)
                    mma_f16(acc[mt][nt], af[mt], bf[nt]);
        }

        __syncthreads();     // all warps done reading slot before refill
        if (c + 2 < NC) issue(c + 2, slot);
        CP_COMMIT();         // uniform group numbering
    }

    // ---- epilogue
    if (mode == 0) {
        #pragma unroll
        for (int mt = 0; mt < 4; mt++) {
            const int row = m0 + wm + mt * 16 + g;
            #pragma unroll
            for (int nt = 0; nt < 8; nt++) {
                const int col = n0 + wn + nt * 8 + tig * 2;
                *(float2*)(C + (size_t)row * N + col) =
                    make_float2(acc[mt][nt][0], acc[mt][nt][1]);
                *(float2*)(C + (size_t)(row + 8) * N + col) =
                    make_float2(acc[mt][nt][2], acc[mt][nt][3]);
            }
        }
    } else if (n0 < DMODEL + NKVH * HDIM) {
        // rope branch: Q (n0 < 2048) or K (2048 <= n0 < 2304)
        const bool isQ = (n0 < DMODEL);
        __half* Out = isQ ? Qout : Kout;
        const int ldo = isQ ? DMODEL : (NKVH * HDIM);
        const int cb  = isQ ? 0 : DMODEL;
        const float scale = isQ ? qscale : 1.0f;
        #pragma unroll
        for (int mt = 0; mt < 4; mt++) {
            const int row = m0 + wm + mt * 16 + g;
            const int s0 = row & (SEQ - 1);
            const int s1 = (row + 8) & (SEQ - 1);
            #pragma unroll
            for (int nt = 0; nt < 8; nt++) {
                const int ccol = n0 + wn + nt * 8 + tig * 2 - cb;
                const int i = (ccol & 63) >> 1;
                float2 cs0 = *(const float2*)(freqs + s0 * HDIM + i * 2);
                float2 cs1 = *(const float2*)(freqs + s1 * HDIM + i * 2);
                float xr = acc[mt][nt][0], xi = acc[mt][nt][1];
                *(uint32_t*)(Out + (size_t)row * ldo + ccol) =
                    packh2((xr * cs0.x - xi * cs0.y) * scale,
                           (xr * cs0.y + xi * cs0.x) * scale);
                xr = acc[mt][nt][2]; xi = acc[mt][nt][3];
                *(uint32_t*)(Out + (size_t)(row + 8) * ldo + ccol) =
                    packh2((xr * cs1.x - xi * cs1.y) * scale,
                           (xr * cs1.y + xi * cs1.x) * scale);
            }
        }
    } else {
        // V columns: write TRANSPOSED directly into vt [256, 4096]
        #pragma unroll
        for (int mt = 0; mt < 4; mt++) {
            const int row = m0 + wm + mt * 16 + g;
            #pragma unroll
            for (int nt = 0; nt < 8; nt++) {
                const int ccol = n0 + wn + nt * 8 + tig * 2 - (DMODEL + NKVH * HDIM);
                VTout[(size_t)ccol * MROWS + row] =
                    __float2half_rn(acc[mt][nt][0]);
                VTout[(size_t)(ccol + 1) * MROWS + row] =
                    __float2half_rn(acc[mt][nt][1]);
                VTout[(size_t)ccol * MROWS + row + 8] =
                    __float2half_rn(acc[mt][nt][2]);
                VTout[(size_t)(ccol + 1) * MROWS + row + 8] =
                    __float2half_rn(acc[mt][nt][3]);
            }
        }
    }
}

// ---------------------------------------------------------------------------
// FlashAttention-2 on fp16 mma.sync. P in registers (C-frag == A-frag layout).
// 3-stage K/V cp.async pipeline, ONE barrier per kt; K/V fragments via LDSM.
// Smem (words): K 3x2304, V 3x2304 = 13824 (55296 B); Q staged in K slots 0-1.
// ---------------------------------------------------------------------------
#define FA_QT 128
#define FA_KT 64
#define FA_THREADS 256
#define FA_STRW 36
#define FA_KSLOT_W (FA_KT * FA_STRW)        // 2304
#define FA_VBASE (3 * FA_KSLOT_W)           // 6912
#define FA_SMEM_W (6 * FA_KSLOT_W)          // 13824
#define FA_SMEM_BYTES (FA_SMEM_W * 4)       // 55296

__global__ __launch_bounds__(FA_THREADS, 2)
void fa_kernel(const __half* __restrict__ Q,
               const __half* __restrict__ K,
               const __half* __restrict__ Vt,
               __half* __restrict__ O)
{
    extern __shared__ uint32_t smf[];
    const uint32_t sbase = smem_u32(smf);

    const int tid  = threadIdx.x;
    const int warp = tid >> 5;
    const int lane = tid & 31;
    const int g    = lane >> 2;
    const int tig  = lane & 3;

    const int qt = (gridDim.x - 1) - blockIdx.x;   // heavy tiles first
    const int h  = blockIdx.y;
    const int b  = blockIdx.z;
    const int kvh = h / GQA_REP;

    const int qrow0 = qt * FA_QT;
    const int wrow  = warp * 16;

    // ldmatrix lane-invariant offsets (B-fragment pattern)
    const int b_row = (lane & 7) + ((lane >> 4) * 8);       // + ntp*16
    const int b_wof = ((lane >> 3) & 1) * 4;                // + k0

    // --- stage Q tile in K-slot-0/1 region (128 rows x 32 words)
    {
        const __half* Qg = Q + (size_t)(b * SEQ + qrow0) * (NHEADS * HDIM) + h * HDIM;
        #pragma unroll
        for (int it = 0; it < 4; it++) {
            int idx = tid + it * FA_THREADS;
            int r = idx >> 3, c = idx & 7;
            *(uint4*)(smf + r * FA_STRW + c * 4) =
                *(const uint4*)(Qg + (size_t)r * (NHEADS * HDIM) + c * 8);
        }
    }
    __syncthreads();

    // --- hoist Q fragments (4 ksteps of k16) via LDSM (A-fragment pattern)
    uint32_t qf[4][4];
    {
        const int a_row = wrow + (lane & 15);
        const int a_wof = (lane >> 4) * 4;
        #pragma unroll
        for (int ks = 0; ks < 4; ks++)
            ldsm4(qf[ks], sbase + 4u * (a_row * FA_STRW + ks * 8 + a_wof));
    }
    __syncthreads();   // Q region freed -> K slots

    const __half* Kb0 = K + (size_t)(b * SEQ) * (NKVH * HDIM) + kvh * HDIM;
    const __half* Vb0 = Vt + (size_t)(kvh * HDIM) * MROWS + b * SEQ;

    auto issue = [&](int kt_, int slot) {
        #pragma unroll
        for (int it = 0; it < 2; it++) {
            int idx = tid + it * FA_THREADS;
            int r = idx >> 3, c = idx & 7;
            cp16(sbase + 4u * (slot * FA_KSLOT_W + r * FA_STRW + c * 4),
                 Kb0 + (size_t)(kt_ * FA_KT + r) * (NKVH * HDIM) + c * 8);
            cp16(sbase + 4u * (FA_VBASE + slot * FA_KSLOT_W + r * FA_STRW + c * 4),
                 Vb0 + (size_t)r * MROWS + kt_ * FA_KT + c * 8);
        }
    };

    const int nkt = 2 * qt + 2;
    issue(0, 0); CP_COMMIT();
    issue(1, 1); CP_COMMIT();

    float m0r = -1e30f, m1r = -1e30f;
    float l0r = 0.0f,  l1r = 0.0f;
    float o[8][4] = {};

    for (int kt = 0; kt < nkt; kt++) {
        CP_WAIT1();
        __syncthreads();   // slot (kt+2)%3 drained; data for kt visible
        if (kt + 2 < nkt) issue(kt + 2, (kt + 2) % 3);
        CP_COMMIT();

        const int slot = kt % 3;
        const uint32_t kS = sbase + 4u * (slot * FA_KSLOT_W);
        const uint32_t vS = sbase + 4u * (FA_VBASE + slot * FA_KSLOT_W);

        const bool active = (kt * FA_KT <= qrow0 + wrow + 15);
        if (active) {
            // S = Q K^T  (K fragments via LDSM)
            float s[8][4] = {};
            #pragma unroll
            for (int ks = 0; ks < 4; ks++) {
                const int k0 = ks * 8;
                uint32_t bf[8][2];
                #pragma unroll
                for (int ntp = 0; ntp < 4; ntp++) {
                    uint32_t t4[4];
                    ldsm4(t4, kS + 4u * ((b_row + ntp * 16) * FA_STRW + k0 + b_wof));
                    bf[2 * ntp][0] = t4[0];
                    bf[2 * ntp][1] = t4[1];
                    bf[2 * ntp + 1][0] = t4[2];
                    bf[2 * ntp + 1][1] = t4[3];
                }
                #pragma unroll
                for (int nt = 0; nt < 8; nt++)
                    mma_f16(s[nt], qf[ks], bf[nt]);
            }

            // causal mask on diagonal-straddling tiles
            if (kt * FA_KT + (FA_KT - 1) > qrow0 + wrow) {
                const int rg  = qrow0 + wrow + g;
                const int rg8 = rg + 8;
                #pragma unroll
                for (int nt = 0; nt < 8; nt++) {
                    const int c0 = kt * FA_KT + nt * 8 + 2 * tig;
                    const int c1 = c0 + 1;
                    if (c0 > rg)  s[nt][0] = -1e30f;
                    if (c1 > rg)  s[nt][1] = -1e30f;
                    if (c0 > rg8) s[nt][2] = -1e30f;
                    if (c1 > rg8) s[nt][3] = -1e30f;
                }
            }

            // online softmax (log2 domain); p overwrites s in registers
            float mx0 = -1e30f, mx1 = -1e30f;
            #pragma unroll
            for (int nt = 0; nt < 8; nt++) {
                mx0 = fmaxf(mx0, fmaxf(s[nt][0], s[nt][1]));
                mx1 = fmaxf(mx1, fmaxf(s[nt][2], s[nt][3]));
            }
            mx0 = fmaxf(mx0, __shfl_xor_sync(0xffffffffu, mx0, 1));
            mx0 = fmaxf(mx0, __shfl_xor_sync(0xffffffffu, mx0, 2));
            mx1 = fmaxf(mx1, __shfl_xor_sync(0xffffffffu, mx1, 1));
            mx1 = fmaxf(mx1, __shfl_xor_sync(0xffffffffu, mx1, 2));

            const float mn0 = fmaxf(m0r, mx0);
            const float mn1 = fmaxf(m1r, mx1);
            const float al0 = fexp2(m0r - mn0);
            const float al1 = fexp2(m1r - mn1);
            m0r = mn0; m1r = mn1;

            float sum0 = 0.0f, sum1 = 0.0f;
            #pragma unroll
            for (int nt = 0; nt < 8; nt++) {
                s[nt][0] = fexp2(s[nt][0] - mn0);
                s[nt][1] = fexp2(s[nt][1] - mn0);
                s[nt][2] = fexp2(s[nt][2] - mn1);
                s[nt][3] = fexp2(s[nt][3] - mn1);
                sum0 += s[nt][0] + s[nt][1];
                sum1 += s[nt][2] + s[nt][3];
            }
            sum0 += __shfl_xor_sync(0xffffffffu, sum0, 1);
            sum0 += __shfl_xor_sync(0xffffffffu, sum0, 2);
            sum1 += __shfl_xor_sync(0xffffffffu, sum1, 1);
            sum1 += __shfl_xor_sync(0xffffffffu, sum1, 2);
            l0r = l0r * al0 + sum0;
            l1r = l1r * al1 + sum1;

            #pragma unroll
            for (int nt = 0; nt < 8; nt++) {
                o[nt][0] *= al0; o[nt][1] *= al0;
                o[nt][2] *= al1; o[nt][3] *= al1;
            }

            // O += P V : P packed straight from registers; V fragments via LDSM
            #pragma unroll
            for (int ks = 0; ks < 4; ks++) {
                const int k0 = ks * 8;
                uint32_t a[4];
                a[0] = packh2(s[2 * ks][0],     s[2 * ks][1]);
                a[1] = packh2(s[2 * ks][2],     s[2 * ks][3]);
                a[2] = packh2(s[2 * ks + 1][0], s[2 * ks + 1][1]);
                a[3] = packh2(s[2 * ks + 1][2], s[2 * ks + 1][3]);
                uint32_t bf[8][2];
                #pragma unroll
                for (int ntp = 0; ntp < 4; ntp++) {
                    uint32_t t4[4];
                    ldsm4(t4, vS + 4u * ((b_row + ntp * 16) * FA_STRW + k0 + b_wof));
                    bf[2 * ntp][0] = t4[0];
                    bf[2 * ntp][1] = t4[1];
                    bf[2 * ntp + 1][0] = t4[2];
                    bf[2 * ntp + 1][1] = t4[3];
                }
                #pragma unroll
                for (int nt = 0; nt < 8; nt++)
                    mma_f16(o[nt], a, bf[nt]);
            }
        }
    }

    // epilogue: normalize, write half (feeds wo GEMM)
    const float il0 = 1.0f / l0r;
    const float il1 = 1.0f / l1r;
    __half* Ob = O + (size_t)(b * SEQ + qrow0 + wrow) * (NHEADS * HDIM) + h * HDIM;
    #pragma unroll
    for (int nt = 0; nt < 8; nt++) {
        *(__half2*)(Ob + (size_t)g * (NHEADS * HDIM) + nt * 8 + 2 * tig) =
            __floats2half2_rn(o[nt][0] * il0, o[nt][1] * il0);
        *(__half2*)(Ob + (size_t)(g + 8) * (NHEADS * HDIM) + nt * 8 + 2 * tig) =
            __floats2half2_rn(o[nt][2] * il1, o[nt][3] * il1);
    }
}

// ---------------------------------------------------------------------------
// launch
// ---------------------------------------------------------------------------
extern "C" void kernel_launch(void* const* d_in, const int* in_sizes, int n_in,
                              void* d_out, int out_size)
{
    const float* x     = (const float*)d_in[0];
    const float* freqs = (const float*)d_in[1];
    // d_in[2] is the additive mask — exactly causal; handled in-kernel.
    const float* wq    = (const float*)d_in[3];
    const float* wk    = (const float*)d_in[4];
    const float* wv    = (const float*)d_in[5];
    const float* wo    = (const float*)d_in[6];
    float* out = (float*)d_out;

    static __half *xh = nullptr, *qh = nullptr, *kh = nullptr,
                  *vt = nullptr, *aoh = nullptr;
    static __half *wqkvTh = nullptr, *woTh = nullptr;
    if (!xh) {
        cudaGetSymbolAddress((void**)&xh,     g_xh);
        cudaGetSymbolAddress((void**)&qh,     g_qh);
        cudaGetSymbolAddress((void**)&kh,     g_kh);
        cudaGetSymbolAddress((void**)&vt,     g_vt);
        cudaGetSymbolAddress((void**)&aoh,    g_aoh);
        cudaGetSymbolAddress((void**)&wqkvTh, g_wqkvTh);
        cudaGetSymbolAddress((void**)&woTh,   g_woTh);
        cudaFuncSetAttribute(mma_gemm_f16_kernel, cudaFuncAttributeMaxDynamicSharedMemorySize,
                             MM_SMEM_BYTES);
        cudaFuncSetAttribute(fa_kernel, cudaFuncAttributeMaxDynamicSharedMemorySize,
                             FA_SMEM_BYTES);
    }

    const float qscale = 0.18033688011112042f;  // 0.125 * log2(e)

    // single prep launch: x conversion + all 4 weight transposes
    prep_kernel<<<dim3(64, 64, 6), dim3(32, 8)>>>(x, wq, wk, wv, wo, xh, wqkvTh, woTh);

    // merged QKV projection (fused rope/scale/half epilogues; V written transposed)
    mma_gemm_f16_kernel<<<dim3(QKVN / MM_BN, MROWS / MM_BM), MM_THREADS, MM_SMEM_BYTES>>>(
        MROWS, QKVN, DMODEL, xh, wqkvTh, nullptr, qh, kh, vt, freqs, 3, qscale);

    // attention
    fa_kernel<<<dim3(SEQ / FA_QT, NHEADS, BATCH), FA_THREADS, FA_SMEM_BYTES>>>(qh, kh, vt, aoh);

    // output projection (fp32 epilogue straight to d_out)
    mma_gemm_f16_kernel<<<dim3(DMODEL / MM_BN, MROWS / MM_BM), MM_THREADS, MM_SMEM_BYTES>>>(
        MROWS, DMODEL, DMODEL, aoh, woTh, out, nullptr, nullptr, nullptr, nullptr, 0, 1.0f);
}